// round 2
// baseline (speedup 1.0000x reference)
#include <cuda_runtime.h>
#include <cstdint>

#define B 8
#define DIM 192
#define Hh 128
#define Ww 128
#define KS 7
#define PAD 3
#define HID 48
#define KK 49          // 7*7
#define PLANE (Hh*Ww)  // 16384
#define OUTW (DIM*KK)  // 9408
#define EPS 1e-5f

// -------- scratch (device globals; no allocation allowed) --------
__device__ float g_pooled[B * DIM];      // [b, c]
__device__ float g_y[B * HID];           // [b, h]
__device__ float g_wdyn[B * OUTW];       // [b, c*49 + k]

// ============================================================
// Kernel 1: global average pool over HxW per (b,c) plane
// grid = B*DIM blocks, 256 threads
// ============================================================
__global__ __launch_bounds__(256) void pool_kernel(const float* __restrict__ x) {
    int bc = blockIdx.x;
    const float4* p = reinterpret_cast<const float4*>(x + (size_t)bc * PLANE);
    float s = 0.f;
    #pragma unroll 4
    for (int i = threadIdx.x; i < PLANE / 4; i += 256) {
        float4 v = p[i];
        s += (v.x + v.y) + (v.z + v.w);
    }
    // warp reduce
    #pragma unroll
    for (int off = 16; off > 0; off >>= 1)
        s += __shfl_down_sync(0xffffffffu, s, off);
    __shared__ float red[8];
    int lane = threadIdx.x & 31, warp = threadIdx.x >> 5;
    if (lane == 0) red[warp] = s;
    __syncthreads();
    if (warp == 0) {
        float t = (lane < 8) ? red[lane] : 0.f;
        #pragma unroll
        for (int off = 4; off > 0; off >>= 1)
            t += __shfl_down_sync(0xffffffffu, t, off);
        if (lane == 0) g_pooled[bc] = t * (1.0f / (float)PLANE);
    }
}

// ============================================================
// Kernel 2a: y = relu(BN(pooled @ w1^T))   [b, HID]
// grid = B blocks, 64 threads (48 active)
// ============================================================
__global__ __launch_bounds__(64) void gen_y_kernel(
    const float* __restrict__ w1,
    const float* __restrict__ gamma, const float* __restrict__ beta,
    const float* __restrict__ mean,  const float* __restrict__ var) {
    int b = blockIdx.x;
    int t = threadIdx.x;
    if (t >= HID) return;
    const float* pr = g_pooled + b * DIM;
    const float* wr = w1 + t * DIM;
    float s = 0.f;
    #pragma unroll 8
    for (int c = 0; c < DIM; c++) s = fmaf(pr[c], wr[c], s);
    s = (s - mean[t]) * rsqrtf(var[t] + EPS) * gamma[t] + beta[t];
    g_y[b * HID + t] = s > 0.f ? s : 0.f;
}

// ============================================================
// Kernel 2b: wdyn[b, o] = y[b,:] . w2[o,:] + b2[o]
// grid = (74, B), 128 threads. Stage w2 chunk into smem (coalesced,
// padded stride 49 -> conflict free).
// ============================================================
#define W2_CHUNK 128
__global__ __launch_bounds__(128) void gen_wdyn_kernel(
    const float* __restrict__ w2, const float* __restrict__ b2) {
    int b = blockIdx.y;
    int obase = blockIdx.x * W2_CHUNK;
    int t = threadIdx.x;

    __shared__ float sy[HID];
    __shared__ float w2s[W2_CHUNK * (HID + 1)];   // pad to 49 floats/row

    if (t < HID) sy[t] = g_y[b * HID + t];

    // coalesced staged load of w2 rows [obase, obase+128)
    const int n_f4 = W2_CHUNK * HID / 4;          // 1536 float4
    const float4* w2v = reinterpret_cast<const float4*>(w2 + (size_t)obase * HID);
    int max_f4 = (OUTW - obase) * HID / 4;        // guard last chunk
    for (int i = t; i < n_f4; i += 128) {
        float4 v = (i < max_f4) ? w2v[i] : make_float4(0.f, 0.f, 0.f, 0.f);
        int row = i / (HID / 4);
        int col = (i % (HID / 4)) * 4;
        float* dst = &w2s[row * (HID + 1) + col];
        dst[0] = v.x; dst[1] = v.y; dst[2] = v.z; dst[3] = v.w;
    }
    __syncthreads();

    int o = obase + t;
    if (o < OUTW) {
        float acc = b2[o];
        const float* wr = &w2s[t * (HID + 1)];
        #pragma unroll
        for (int h = 0; h < HID; h++) acc = fmaf(sy[h], wr[h], acc);
        g_wdyn[(size_t)b * OUTW + o] = acc;
    }
}

// ============================================================
// Kernel 3: per-sample depthwise 7x7 conv + bias
// grid = (B*DIM, 4): one (b,c) plane x one 32-row strip per block.
// 256 threads: tid&127 = column, tid>>7 picks 16-row half.
// Shared tile 38 x 134 (stride 136). Weights in registers.
// Per thread: slide over 22 input rows; 7 LDS + <=49 FFMA per row.
// ============================================================
#define STRIP 32
#define TROWS (STRIP + KS - 1)   // 38
#define TCOLS (Ww + KS - 1)      // 134
#define TSTRIDE 136
#define RPT 16                   // output rows per thread

__global__ __launch_bounds__(256) void dwconv_kernel(
    const float* __restrict__ x, const float* __restrict__ bias,
    float* __restrict__ out) {
    int bc = blockIdx.x;             // b*DIM + c
    int strip = blockIdx.y;
    int c = bc % DIM;
    int r0 = strip * STRIP;

    __shared__ float tile[TROWS * TSTRIDE];
    __shared__ float wsh[KK];

    int tid = threadIdx.x;
    if (tid < KK) wsh[tid] = g_wdyn[(size_t)bc * KK + tid];

    const float* plane = x + (size_t)bc * PLANE;
    for (int idx = tid; idx < TROWS * TCOLS; idx += 256) {
        int rr = idx / TCOLS, cc = idx % TCOLS;
        int gr = r0 + rr - PAD, gc = cc - PAD;
        float v = 0.f;
        if (gr >= 0 && gr < Hh && gc >= 0 && gc < Ww)
            v = plane[gr * Ww + gc];
        tile[rr * TSTRIDE + cc] = v;
    }
    __syncthreads();

    float w[KK];
    #pragma unroll
    for (int i = 0; i < KK; i++) w[i] = wsh[i];

    int xcol = tid & (Ww - 1);
    int rbase = (tid >> 7) * RPT;    // 0 or 16 within strip

    float bia = bias[c];
    float acc[RPT];
    #pragma unroll
    for (int i = 0; i < RPT; i++) acc[i] = bia;

    #pragma unroll
    for (int ir = 0; ir < RPT + KS - 1; ir++) {     // 22 tile rows
        float v[KS];
        const float* trow = &tile[(rbase + ir) * TSTRIDE + xcol];
        #pragma unroll
        for (int kw = 0; kw < KS; kw++) v[kw] = trow[kw];
        #pragma unroll
        for (int kh = 0; kh < KS; kh++) {
            int orr = ir - kh;
            if (orr >= 0 && orr < RPT) {
                float s = acc[orr];
                #pragma unroll
                for (int kw = 0; kw < KS; kw++)
                    s = fmaf(v[kw], w[kh * KS + kw], s);
                acc[orr] = s;
            }
        }
    }

    float* op = out + (size_t)bc * PLANE + (size_t)(r0 + rbase) * Ww + xcol;
    #pragma unroll
    for (int i = 0; i < RPT; i++) op[(size_t)i * Ww] = acc[i];
}

// ============================================================
// launch
// inputs: 0:x 1:w1 2:bn_gamma 3:bn_beta 4:bn_mean 5:bn_var 6:w2 7:b2 8:bias
// ============================================================
extern "C" void kernel_launch(void* const* d_in, const int* in_sizes, int n_in,
                              void* d_out, int out_size) {
    const float* x     = (const float*)d_in[0];
    const float* w1    = (const float*)d_in[1];
    const float* gamma = (const float*)d_in[2];
    const float* beta  = (const float*)d_in[3];
    const float* mean  = (const float*)d_in[4];
    const float* var   = (const float*)d_in[5];
    const float* w2    = (const float*)d_in[6];
    const float* b2    = (const float*)d_in[7];
    const float* bias  = (const float*)d_in[8];
    float* out = (float*)d_out;

    pool_kernel<<<B * DIM, 256>>>(x);
    gen_y_kernel<<<B, 64>>>(w1, gamma, beta, mean, var);
    dim3 g2((OUTW + W2_CHUNK - 1) / W2_CHUNK, B);
    gen_wdyn_kernel<<<g2, 128>>>(w2, b2);
    dim3 g3(B * DIM, Hh / STRIP);
    dwconv_kernel<<<g3, 256>>>(x, bias, out);
}